// round 9
// baseline (speedup 1.0000x reference)
#include <cuda_runtime.h>
#include <cuda_bf16.h>
#include <math.h>
#include <float.h>

// Problem constants
#define BB   4
#define LL   2048
#define KNB  30
#define IND  128
#define OUTD 400
#define NROW (BB*LL)            // 8192

// Scratch (device globals; no allocation allowed)
__device__ __align__(16) float g_A [NROW*OUTD];   // V@W1 + bias
__device__ __align__(16) float g_Bm[NROW*OUTD];   // V@W2
__device__ int g_E[NROW*KNB];

#define KEYMAX 0xFFFFFFFFFFFFFFFFull

// convert an sq-domain key to sqrt-domain (only in the allValid fast path)
#define CVT(T) do { if (allValid && (T) != KEYMAX) {                         \
    float s_ = __uint_as_float((unsigned)((T) >> 11));                       \
    unsigned j_ = (unsigned)((T) & 2047u);                                   \
    (T) = ((unsigned long long)__float_as_uint(sqrtf(s_)) << 11) | j_; } } while (0)
#define SW(a,b) do { if ((a) > (b)) { unsigned long long t_=(a); (a)=(b); (b)=t_; } } while (0)

// ---------------------------------------------------------------------------
// KNN: one warp per query, 8 queries (warps) per block.
// Lane l owns candidates j = c*32 + l (conflict-free LDS.128).
// Hot loop builds per-lane top-4 by SQUARED distance (no sqrt); survivors are
// converted to sqrt-keys + sorted, so the 30 selection rounds use exact
// lax.top_k (sqrt value, index) tie semantics.
// ---------------------------------------------------------------------------
__global__ __launch_bounds__(256) void knn_kernel(const float* __restrict__ X,
                           const float* __restrict__ mask,
                           float* __restrict__ tail, int writeTail)
{
    __shared__ float4 sX[LL];        // (x, y, z, mask)  32 KB
    __shared__ int sAllValid;

    int tid  = threadIdx.x;
    int w    = tid >> 5;
    int lane = tid & 31;
    int qblock = blockIdx.x * 8;
    int b = qblock >> 11;            // 8 queries per block never cross a batch

    if (tid == 0) sAllValid = 1;
    __syncthreads();

    int ok = 1;
    for (int j = tid; j < LL; j += 256) {
        const float* xr = X + ((size_t)(b*LL + j))*12 + 3;
        float mv = mask[b*LL + j];
        sX[j] = make_float4(xr[0], xr[1], xr[2], mv);
        ok &= (mv == 1.0f);
    }
    if (!ok) sAllValid = 0;
    __syncthreads();

    const int allValid = sAllValid;

    int q = qblock + w;
    int i = q & (LL-1);
    float4 qp = sX[i];
    float qx = qp.x, qy = qp.y, qz = qp.z;
    bool qvalid = allValid || (qp.w > 0.5f);

    // masked-case row max (skipped entirely when the whole batch is valid)
    float dmax = 0.f;
    if (!allValid) {
        float maxsq = -1.f;
        for (int c = 0; c < 64; c++) {
            int j = c*32 + lane;
            float4 p = sX[j];
            float dx = p.x-qx, dy = p.y-qy, dz = p.z-qz;
            float sq = fmaf(dx,dx, fmaf(dy,dy, fmaf(dz,dz, 1e-6f)));
            if (qvalid && (p.w > 0.5f)) maxsq = fmaxf(maxsq, sq);
        }
        #pragma unroll
        for (int off = 16; off; off >>= 1)
            maxsq = fmaxf(maxsq, __shfl_xor_sync(0xffffffffu, maxsq, off));
        dmax = (maxsq > 0.f) ? sqrtf(maxsq) : 0.f;
    }

    // hot loop: per-lane sorted top-4 (ascending) of packed keys
    unsigned long long T0 = KEYMAX, T1 = KEYMAX, T2 = KEYMAX, T3 = KEYMAX;
    #pragma unroll 8
    for (int c = 0; c < 64; c++) {
        int j = c*32 + lane;
        float4 p = sX[j];
        float dx = p.x-qx, dy = p.y-qy, dz = p.z-qz;
        float sq = fmaf(dx,dx, fmaf(dy,dy, fmaf(dz,dz, 1e-6f)));
        float dv;
        if (allValid) dv = sq;                           // sqrt deferred
        else dv = (qvalid && (p.w > 0.5f)) ? sqrtf(sq) : dmax;
        unsigned long long key =
            ((unsigned long long)__float_as_uint(dv) << 11) | (unsigned)j;
        if (key < T3) {
            T3 = key;
            if (T3 < T2) { unsigned long long t=T2; T2=T3; T3=t; }
            if (T2 < T1) { unsigned long long t=T1; T1=T2; T2=t; }
            if (T1 < T0) { unsigned long long t=T0; T0=T1; T1=t; }
        }
    }
    // convert survivors to sqrt-domain keys and restore exact order
    CVT(T0); CVT(T1); CVT(T2); CVT(T3);
    SW(T0,T1); SW(T2,T3); SW(T0,T2); SW(T1,T3); SW(T1,T2);

    unsigned long long popped = 0ull;

    #pragma unroll 1
    for (int k = 0; k < KNB; k++) {
        unsigned long long v = T0;
        #pragma unroll
        for (int off = 16; off; off >>= 1) {
            unsigned long long o = __shfl_xor_sync(0xffffffffu, v, off);
            if (o < v) v = o;
        }
        int wj = (int)(v & 2047u);
        if (lane == 0) {
            g_E[q*KNB + k] = wj;
            if (writeTail) tail[q*KNB + k] = (float)wj;
        }
        if ((wj & 31) == lane) {         // owner pops its head
            popped |= 1ull << (wj >> 5);
            T0 = T1; T1 = T2; T2 = T3; T3 = KEYMAX;
            if (T0 == KEYMAX) {
                // refill (rare): rescan un-popped candidates
                for (int c = 0; c < 64; c++) {
                    if (popped & (1ull << c)) continue;
                    int j = c*32 + lane;
                    float4 p = sX[j];
                    float dx = p.x-qx, dy = p.y-qy, dz = p.z-qz;
                    float sq = fmaf(dx,dx, fmaf(dy,dy, fmaf(dz,dz, 1e-6f)));
                    float dv;
                    if (allValid) dv = sq;
                    else dv = (qvalid && (p.w > 0.5f)) ? sqrtf(sq) : dmax;
                    unsigned long long key =
                        ((unsigned long long)__float_as_uint(dv) << 11) | (unsigned)j;
                    if (key < T3) {
                        T3 = key;
                        if (T3 < T2) { unsigned long long t=T2; T2=T3; T3=t; }
                        if (T2 < T1) { unsigned long long t=T1; T1=T2; T2=t; }
                        if (T1 < T0) { unsigned long long t=T0; T0=T1; T1=t; }
                    }
                }
                CVT(T0); CVT(T1); CVT(T2); CVT(T3);
                SW(T0,T1); SW(T2,T3); SW(T0,T2); SW(T1,T3); SW(T1,T2);
            }
        }
    }
}

// ---------------------------------------------------------------------------
// GEMM: g_A = V @ W[:128] + bias ; g_Bm = V @ W[128:]
// ---------------------------------------------------------------------------
__global__ void gemm_kernel(const float* __restrict__ V,
                            const float* __restrict__ W,
                            const float* __restrict__ bias)
{
    __shared__ float sV[16][132];
    __shared__ float sW[16][64];

    int rb   = blockIdx.x * 128;
    int cb   = blockIdx.y;
    int half = (cb >= 7) ? 1 : 0;
    int o0   = (cb - half*7) * 64;
    int koff = half * 128;
    float* out = half ? g_Bm : g_A;

    int tid = threadIdx.x;
    int ty = tid >> 4;
    int tx = tid & 15;

    float acc[8][4];
    #pragma unroll
    for (int r = 0; r < 8; r++)
        #pragma unroll
        for (int c = 0; c < 4; c++) acc[r][c] = 0.f;

    for (int kt = 0; kt < IND; kt += 16) {
        {
            int rr = tid & 127;
            int v  = tid >> 7;
            const float* src = V + (size_t)(rb + rr)*IND + kt + v*8;
            float4 a  = *(const float4*)src;
            float4 b2 = *(const float4*)(src + 4);
            int kk = v * 8;
            sV[kk+0][rr]=a.x;  sV[kk+1][rr]=a.y;  sV[kk+2][rr]=a.z;  sV[kk+3][rr]=a.w;
            sV[kk+4][rr]=b2.x; sV[kk+5][rr]=b2.y; sV[kk+6][rr]=b2.z; sV[kk+7][rr]=b2.w;
        }
        {
            int kk = tid >> 4;
            int cc = (tid & 15) * 4;
            int o  = o0 + cc;
            const float* wrow = W + (size_t)(kt + kk + koff)*OUTD;
            float4 wv;
            if (o + 3 < OUTD) {
                wv = *(const float4*)(wrow + o);
            } else {
                wv.x = (o+0 < OUTD) ? wrow[o+0] : 0.f;
                wv.y = (o+1 < OUTD) ? wrow[o+1] : 0.f;
                wv.z = (o+2 < OUTD) ? wrow[o+2] : 0.f;
                wv.w = (o+3 < OUTD) ? wrow[o+3] : 0.f;
            }
            *(float4*)&sW[kk][cc] = wv;
        }
        __syncthreads();

        #pragma unroll
        for (int kk = 0; kk < 16; kk++) {
            float rv[8];
            *(float4*)&rv[0] = *(const float4*)&sV[kk][ty*8];
            *(float4*)&rv[4] = *(const float4*)&sV[kk][ty*8 + 4];
            float4 wv = *(const float4*)&sW[kk][tx*4];
            #pragma unroll
            for (int r = 0; r < 8; r++) {
                acc[r][0] += rv[r] * wv.x;
                acc[r][1] += rv[r] * wv.y;
                acc[r][2] += rv[r] * wv.z;
                acc[r][3] += rv[r] * wv.w;
            }
        }
        __syncthreads();
    }

    #pragma unroll
    for (int r = 0; r < 8; r++) {
        int row = rb + ty*8 + r;
        #pragma unroll
        for (int c = 0; c < 4; c++) {
            int o = o0 + tx*4 + c;
            if (o < OUTD) {
                float val = acc[r][c];
                if (!half) val += bias[o];
                out[(size_t)row*OUTD + o] = val;
            }
        }
    }
}

// ---------------------------------------------------------------------------
// Assembly: out[q,k,:] = A[row_i0,:] + Bm[row_jk,:]   (float4 vectorized)
// ---------------------------------------------------------------------------
__global__ void assemble_kernel(float* __restrict__ out)
{
    __shared__ float4 sA[100];
    __shared__ int    sI[KNB];

    int q   = blockIdx.x;
    int b   = q >> 11;
    int tid = threadIdx.x;

    if (tid < KNB) sI[tid] = g_E[q*KNB + tid];
    __syncthreads();
    int e0 = sI[0];
    if (tid < 100)
        sA[tid] = ((const float4*)g_A)[(size_t)((b << 11) + e0)*100 + tid];
    __syncthreads();

    float4* out4 = (float4*)out + (size_t)q * (KNB*100);
    const float4* B4 = (const float4*)g_Bm;

    #pragma unroll 4
    for (int id = tid; id < KNB*100; id += 256) {
        int k = id / 100;
        int c = id - k*100;
        int rj = (b << 11) + sI[k];
        float4 a  = sA[c];
        float4 bb = __ldg(&B4[(size_t)rj*100 + c]);
        float4 r;
        r.x = a.x + bb.x; r.y = a.y + bb.y;
        r.z = a.z + bb.z; r.w = a.w + bb.w;
        out4[id] = r;
    }
}

// ---------------------------------------------------------------------------
extern "C" void kernel_launch(void* const* d_in, const int* in_sizes, int n_in,
                              void* d_out, int out_size)
{
    const float* X    = (const float*)d_in[0];
    const float* mask = (const float*)d_in[1];
    const float* V    = (const float*)d_in[2];
    const float* W    = (const float*)d_in[3];
    const float* bias = (const float*)d_in[4];
    float* out = (float*)d_out;

    const long long HEV  = (long long)NROW * KNB * OUTD;  // 98,304,000
    const long long EIDX = (long long)NROW * KNB;         // 245,760
    int writeTail = ((long long)out_size >= HEV + EIDX) ? 1 : 0;
    float* tail = writeTail ? (out + HEV) : nullptr;

    // one-time side-stream setup (no device memory involved)
    static cudaStream_t s2 = nullptr;
    static cudaEvent_t eFork = nullptr, eJoin = nullptr;
    static int streamsOK = -1;
    if (streamsOK < 0) {
        streamsOK = 1;
        if (cudaStreamCreateWithFlags(&s2, cudaStreamNonBlocking) != cudaSuccess) streamsOK = 0;
        if (streamsOK && cudaEventCreateWithFlags(&eFork, cudaEventDisableTiming) != cudaSuccess) streamsOK = 0;
        if (streamsOK && cudaEventCreateWithFlags(&eJoin, cudaEventDisableTiming) != cudaSuccess) streamsOK = 0;
    }

    if (streamsOK) {
        // fork: gemm runs concurrently with knn
        cudaEventRecord(eFork, 0);
        cudaStreamWaitEvent(s2, eFork, 0);
        knn_kernel<<<NROW/8, 256>>>(X, mask, tail, writeTail);
        gemm_kernel<<<dim3(NROW/128, 14), 256, 0, s2>>>(V, W, bias);
        cudaEventRecord(eJoin, s2);
        cudaStreamWaitEvent(0, eJoin, 0);
        assemble_kernel<<<NROW, 256>>>(out);
    } else {
        knn_kernel<<<NROW/8, 256>>>(X, mask, tail, writeTail);
        gemm_kernel<<<dim3(NROW/128, 14), 256>>>(V, W, bias);
        assemble_kernel<<<NROW, 256>>>(out);
    }
}

// round 10
// speedup vs baseline: 1.1095x; 1.1095x over previous
#include <cuda_runtime.h>
#include <cuda_bf16.h>
#include <math.h>
#include <float.h>

// Problem constants
#define BB   4
#define LL   2048
#define KNB  30
#define IND  128
#define OUTD 400
#define NROW (BB*LL)            // 8192

// Scratch (device globals; no allocation allowed)
__device__ __align__(16) float g_A [NROW*OUTD];   // V@W1 + bias
__device__ __align__(16) float g_Bm[NROW*OUTD];   // V@W2
__device__ int g_E[NROW*KNB];

#define JSENT 2047

// lexicographic (f, j) compare-swap (stable for equal f by index)
#define SWP(fa,ja,fb,jb) do {                                        \
    if ((fa) > (fb) || ((fa) == (fb) && (ja) > (jb))) {              \
        float tf_=(fa); (fa)=(fb); (fb)=tf_;                         \
        int   tj_=(ja); (ja)=(jb); (jb)=tj_; }                       \
} while (0)

// ---------------------------------------------------------------------------
// KNN: one warp per query, 8 queries (warps) per block.
// Lane l owns candidates j = c*32 + l (conflict-free LDS.128).
// Hot loop: per-lane top-4 by SQUARED distance in plain (float,int) registers
// (no 64-bit keys, no sqrt). j strictly increases in the scan, so strict
// float compares reproduce exact (value, index) lexicographic semantics.
// Survivors get sqrt + (f,j) re-sort; selection = 30 rounds of two REDUX.MIN.
// ---------------------------------------------------------------------------
__global__ __launch_bounds__(256) void knn_kernel(const float* __restrict__ X,
                           const float* __restrict__ mask,
                           float* __restrict__ tail, int writeTail)
{
    __shared__ float4 sX[LL];        // (x, y, z, mask)  32 KB
    __shared__ int sAllValid;

    int tid  = threadIdx.x;
    int w    = tid >> 5;
    int lane = tid & 31;
    int qblock = blockIdx.x * 8;
    int b = qblock >> 11;            // 8 queries per block never cross a batch

    if (tid == 0) sAllValid = 1;
    __syncthreads();

    int ok = 1;
    for (int j = tid; j < LL; j += 256) {
        const float* xr = X + ((size_t)(b*LL + j))*12 + 3;
        float mv = mask[b*LL + j];
        sX[j] = make_float4(xr[0], xr[1], xr[2], mv);
        ok &= (mv == 1.0f);
    }
    if (!ok) sAllValid = 0;
    __syncthreads();

    const int allValid = sAllValid;

    int q = qblock + w;
    int i = q & (LL-1);
    float4 qp = sX[i];
    float qx = qp.x, qy = qp.y, qz = qp.z;
    bool qvalid = allValid || (qp.w > 0.5f);

    // masked-case row max (skipped entirely when the whole batch is valid)
    float dmax = 0.f;
    if (!allValid) {
        float maxsq = -1.f;
        for (int c = 0; c < 64; c++) {
            int j = c*32 + lane;
            float4 p = sX[j];
            float dx = p.x-qx, dy = p.y-qy, dz = p.z-qz;
            float sq = fmaf(dx,dx, fmaf(dy,dy, fmaf(dz,dz, 1e-6f)));
            if (qvalid && (p.w > 0.5f)) maxsq = fmaxf(maxsq, sq);
        }
        #pragma unroll
        for (int off = 16; off; off >>= 1)
            maxsq = fmaxf(maxsq, __shfl_xor_sync(0xffffffffu, maxsq, off));
        dmax = (maxsq > 0.f) ? sqrtf(maxsq) : 0.f;
    }

    // hot loop: per-lane sorted top-4 ascending by (f, j); f is sq (allValid)
    float f0 = FLT_MAX, f1 = FLT_MAX, f2 = FLT_MAX, f3 = FLT_MAX;
    int   j0 = JSENT,   j1 = JSENT,   j2 = JSENT,   j3 = JSENT;
    #pragma unroll 8
    for (int c = 0; c < 64; c++) {
        int j = c*32 + lane;
        float4 p = sX[j];
        float dx = p.x-qx, dy = p.y-qy, dz = p.z-qz;
        float sq = fmaf(dx,dx, fmaf(dy,dy, fmaf(dz,dz, 1e-6f)));
        float dv;
        if (allValid) dv = sq;                           // sqrt deferred
        else dv = (qvalid && (p.w > 0.5f)) ? sqrtf(sq) : dmax;
        if (dv < f3) {
            f3 = dv; j3 = j;
            if (f3 < f2) { float t=f2; f2=f3; f3=t; int u=j2; j2=j3; j3=u; }
            if (f2 < f1) { float t=f1; f1=f2; f2=t; int u=j1; j1=j2; j2=u; }
            if (f1 < f0) { float t=f0; f0=f1; f1=t; int u=j0; j0=j1; j1=u; }
        }
    }
    // convert survivors to sqrt domain and restore exact (f, j) order
    if (allValid) { f0 = sqrtf(f0); f1 = sqrtf(f1); f2 = sqrtf(f2); f3 = sqrtf(f3); }
    SWP(f0,j0,f1,j1); SWP(f2,j2,f3,j3); SWP(f0,j0,f2,j2); SWP(f1,j1,f3,j3); SWP(f1,j1,f2,j2);

    unsigned long long popped = 0ull;

    #pragma unroll 1
    for (int k = 0; k < KNB; k++) {
        unsigned kf = __float_as_uint(f0);              // nonneg -> monotone bits
        unsigned m  = __reduce_min_sync(0xffffffffu, kf);
        unsigned cand = (kf == m) ? (unsigned)j0 : 0xFFFFFFFFu;
        unsigned wj = __reduce_min_sync(0xffffffffu, cand);
        if (lane == 0) {
            g_E[q*KNB + k] = (int)wj;
            if (writeTail) tail[q*KNB + k] = (float)wj;
        }
        if ((wj & 31u) == (unsigned)lane) {             // owner pops its head
            popped |= 1ull << (wj >> 5);
            f0=f1; j0=j1; f1=f2; j1=j2; f2=f3; j2=j3; f3=FLT_MAX; j3=JSENT;
            if (f0 == FLT_MAX) {
                // refill (rare): rescan un-popped candidates
                for (int c = 0; c < 64; c++) {
                    if (popped & (1ull << c)) continue;
                    int j = c*32 + lane;
                    float4 p = sX[j];
                    float dx = p.x-qx, dy = p.y-qy, dz = p.z-qz;
                    float sq = fmaf(dx,dx, fmaf(dy,dy, fmaf(dz,dz, 1e-6f)));
                    float dv;
                    if (allValid) dv = sq;
                    else dv = (qvalid && (p.w > 0.5f)) ? sqrtf(sq) : dmax;
                    if (dv < f3) {
                        f3 = dv; j3 = j;
                        if (f3 < f2) { float t=f2; f2=f3; f3=t; int u=j2; j2=j3; j3=u; }
                        if (f2 < f1) { float t=f1; f1=f2; f2=t; int u=j1; j1=j2; j2=u; }
                        if (f1 < f0) { float t=f0; f0=f1; f1=t; int u=j0; j0=j1; j1=u; }
                    }
                }
                if (allValid) { f0=sqrtf(f0); f1=sqrtf(f1); f2=sqrtf(f2); f3=sqrtf(f3); }
                SWP(f0,j0,f1,j1); SWP(f2,j2,f3,j3); SWP(f0,j0,f2,j2);
                SWP(f1,j1,f3,j3); SWP(f1,j1,f2,j2);
            }
        }
    }
}

// ---------------------------------------------------------------------------
// GEMM: g_A = V @ W[:128] + bias ; g_Bm = V @ W[128:]
// ---------------------------------------------------------------------------
__global__ void gemm_kernel(const float* __restrict__ V,
                            const float* __restrict__ W,
                            const float* __restrict__ bias)
{
    __shared__ float sV[16][132];
    __shared__ float sW[16][64];

    int rb   = blockIdx.x * 128;
    int cb   = blockIdx.y;
    int half = (cb >= 7) ? 1 : 0;
    int o0   = (cb - half*7) * 64;
    int koff = half * 128;
    float* out = half ? g_Bm : g_A;

    int tid = threadIdx.x;
    int ty = tid >> 4;
    int tx = tid & 15;

    float acc[8][4];
    #pragma unroll
    for (int r = 0; r < 8; r++)
        #pragma unroll
        for (int c = 0; c < 4; c++) acc[r][c] = 0.f;

    for (int kt = 0; kt < IND; kt += 16) {
        {
            int rr = tid & 127;
            int v  = tid >> 7;
            const float* src = V + (size_t)(rb + rr)*IND + kt + v*8;
            float4 a  = *(const float4*)src;
            float4 b2 = *(const float4*)(src + 4);
            int kk = v * 8;
            sV[kk+0][rr]=a.x;  sV[kk+1][rr]=a.y;  sV[kk+2][rr]=a.z;  sV[kk+3][rr]=a.w;
            sV[kk+4][rr]=b2.x; sV[kk+5][rr]=b2.y; sV[kk+6][rr]=b2.z; sV[kk+7][rr]=b2.w;
        }
        {
            int kk = tid >> 4;
            int cc = (tid & 15) * 4;
            int o  = o0 + cc;
            const float* wrow = W + (size_t)(kt + kk + koff)*OUTD;
            float4 wv;
            if (o + 3 < OUTD) {
                wv = *(const float4*)(wrow + o);
            } else {
                wv.x = (o+0 < OUTD) ? wrow[o+0] : 0.f;
                wv.y = (o+1 < OUTD) ? wrow[o+1] : 0.f;
                wv.z = (o+2 < OUTD) ? wrow[o+2] : 0.f;
                wv.w = (o+3 < OUTD) ? wrow[o+3] : 0.f;
            }
            *(float4*)&sW[kk][cc] = wv;
        }
        __syncthreads();

        #pragma unroll
        for (int kk = 0; kk < 16; kk++) {
            float rv[8];
            *(float4*)&rv[0] = *(const float4*)&sV[kk][ty*8];
            *(float4*)&rv[4] = *(const float4*)&sV[kk][ty*8 + 4];
            float4 wv = *(const float4*)&sW[kk][tx*4];
            #pragma unroll
            for (int r = 0; r < 8; r++) {
                acc[r][0] += rv[r] * wv.x;
                acc[r][1] += rv[r] * wv.y;
                acc[r][2] += rv[r] * wv.z;
                acc[r][3] += rv[r] * wv.w;
            }
        }
        __syncthreads();
    }

    #pragma unroll
    for (int r = 0; r < 8; r++) {
        int row = rb + ty*8 + r;
        #pragma unroll
        for (int c = 0; c < 4; c++) {
            int o = o0 + tx*4 + c;
            if (o < OUTD) {
                float val = acc[r][c];
                if (!half) val += bias[o];
                out[(size_t)row*OUTD + o] = val;
            }
        }
    }
}

// ---------------------------------------------------------------------------
// Assembly: out[q,k,:] = A[row_i0,:] + Bm[row_jk,:]
// 2 queries per 512-thread block; streaming stores (__stcs) keep the 393MB
// output from evicting the L2-resident gather tables.
// ---------------------------------------------------------------------------
__global__ __launch_bounds__(512) void assemble_kernel(float* __restrict__ out)
{
    __shared__ float4 sA[2][100];
    __shared__ int    sI[2][KNB];

    int tid  = threadIdx.x;
    int half = tid >> 8;            // which query within block
    int t    = tid & 255;
    int q    = blockIdx.x * 2 + half;
    int b    = q >> 11;

    if (t < KNB) sI[half][t] = g_E[q*KNB + t];
    __syncthreads();
    int e0 = sI[half][0];
    if (t < 100)
        sA[half][t] = ((const float4*)g_A)[(size_t)((b << 11) + e0)*100 + t];
    __syncthreads();

    float4* out4 = (float4*)out + (size_t)q * (KNB*100);
    const float4* B4 = (const float4*)g_Bm;

    #pragma unroll 4
    for (int id = t; id < KNB*100; id += 256) {
        int k = id / 100;
        int c = id - k*100;
        int rj = (b << 11) + sI[half][k];
        float4 a  = sA[half][c];
        float4 bb = __ldg(&B4[(size_t)rj*100 + c]);
        float4 r;
        r.x = a.x + bb.x; r.y = a.y + bb.y;
        r.z = a.z + bb.z; r.w = a.w + bb.w;
        __stcs(&out4[id], r);
    }
}

// ---------------------------------------------------------------------------
extern "C" void kernel_launch(void* const* d_in, const int* in_sizes, int n_in,
                              void* d_out, int out_size)
{
    const float* X    = (const float*)d_in[0];
    const float* mask = (const float*)d_in[1];
    const float* V    = (const float*)d_in[2];
    const float* W    = (const float*)d_in[3];
    const float* bias = (const float*)d_in[4];
    float* out = (float*)d_out;

    const long long HEV  = (long long)NROW * KNB * OUTD;  // 98,304,000
    const long long EIDX = (long long)NROW * KNB;         // 245,760
    int writeTail = ((long long)out_size >= HEV + EIDX) ? 1 : 0;
    float* tail = writeTail ? (out + HEV) : nullptr;

    // one-time side-stream setup (no device memory involved)
    static cudaStream_t s2 = nullptr;
    static cudaEvent_t eFork = nullptr, eJoin = nullptr;
    static int streamsOK = -1;
    if (streamsOK < 0) {
        streamsOK = 1;
        if (cudaStreamCreateWithFlags(&s2, cudaStreamNonBlocking) != cudaSuccess) streamsOK = 0;
        if (streamsOK && cudaEventCreateWithFlags(&eFork, cudaEventDisableTiming) != cudaSuccess) streamsOK = 0;
        if (streamsOK && cudaEventCreateWithFlags(&eJoin, cudaEventDisableTiming) != cudaSuccess) streamsOK = 0;
    }

    if (streamsOK) {
        // fork: gemm runs concurrently with knn
        cudaEventRecord(eFork, 0);
        cudaStreamWaitEvent(s2, eFork, 0);
        knn_kernel<<<NROW/8, 256>>>(X, mask, tail, writeTail);
        gemm_kernel<<<dim3(NROW/128, 14), 256, 0, s2>>>(V, W, bias);
        cudaEventRecord(eJoin, s2);
        cudaStreamWaitEvent(0, eJoin, 0);
        assemble_kernel<<<NROW/2, 512>>>(out);
    } else {
        knn_kernel<<<NROW/8, 256>>>(X, mask, tail, writeTail);
        gemm_kernel<<<dim3(NROW/128, 14), 256>>>(V, W, bias);
        assemble_kernel<<<NROW/2, 512>>>(out);
    }
}

// round 11
// speedup vs baseline: 1.1323x; 1.0206x over previous
#include <cuda_runtime.h>
#include <cuda_bf16.h>
#include <math.h>
#include <float.h>

// Problem constants
#define BB   4
#define LL   2048
#define KNB  30
#define IND  128
#define OUTD 400
#define NROW (BB*LL)            // 8192

// Scratch (device globals; no allocation allowed)
__device__ __align__(16) float g_A [NROW*OUTD];   // V@W1 + bias
__device__ __align__(16) float g_Bm[NROW*OUTD];   // V@W2
__device__ int g_E[NROW*KNB];

#define JSENT 2047

// lexicographic (f, j) compare-swap (stable for equal f by index)
#define SWP(fa,ja,fb,jb) do {                                        \
    if ((fa) > (fb) || ((fa) == (fb) && (ja) > (jb))) {              \
        float tf_=(fa); (fa)=(fb); (fb)=tf_;                         \
        int   tj_=(ja); (ja)=(jb); (jb)=tj_; }                       \
} while (0)

// ---------------------------------------------------------------------------
// KNN: one warp per query, 16 queries (warps) per 512-thread block.
// grid = 512 blocks; __launch_bounds__(512,4) => 4 blocks/SM => 592 slots
// >= 512 blocks => SINGLE WAVE (kills the 2x wave-quantization tail).
// Lane l owns candidates j = c*32 + l (conflict-free LDS.128).
// Hot loop: per-lane top-4 by squared distance in (float,int) registers;
// j strictly increases in the scan so strict float compares reproduce exact
// (value, index) lexicographic semantics. Survivors get sqrt + re-sort;
// selection = 30 rounds of two REDUX.MIN.
// ---------------------------------------------------------------------------
__global__ __launch_bounds__(512, 4) void knn_kernel(const float* __restrict__ X,
                           const float* __restrict__ mask,
                           float* __restrict__ tail, int writeTail)
{
    __shared__ float4 sX[LL];        // (x, y, z, mask)  32 KB
    __shared__ int sAllValid;

    int tid  = threadIdx.x;
    int w    = tid >> 5;             // 0..15
    int lane = tid & 31;
    int qblock = blockIdx.x * 16;
    int b = qblock >> 11;            // 128 blocks per batch: never crosses

    if (tid == 0) sAllValid = 1;
    __syncthreads();

    int ok = 1;
    for (int j = tid; j < LL; j += 512) {
        const float* xr = X + ((size_t)(b*LL + j))*12 + 3;
        float mv = mask[b*LL + j];
        sX[j] = make_float4(xr[0], xr[1], xr[2], mv);
        ok &= (mv == 1.0f);
    }
    if (!ok) sAllValid = 0;
    __syncthreads();

    const int allValid = sAllValid;

    int q = qblock + w;
    int i = q & (LL-1);
    float4 qp = sX[i];
    float qx = qp.x, qy = qp.y, qz = qp.z;
    bool qvalid = allValid || (qp.w > 0.5f);

    // masked-case row max (skipped entirely when the whole batch is valid)
    float dmax = 0.f;
    if (!allValid) {
        float maxsq = -1.f;
        for (int c = 0; c < 64; c++) {
            int j = c*32 + lane;
            float4 p = sX[j];
            float dx = p.x-qx, dy = p.y-qy, dz = p.z-qz;
            float sq = fmaf(dx,dx, fmaf(dy,dy, fmaf(dz,dz, 1e-6f)));
            if (qvalid && (p.w > 0.5f)) maxsq = fmaxf(maxsq, sq);
        }
        #pragma unroll
        for (int off = 16; off; off >>= 1)
            maxsq = fmaxf(maxsq, __shfl_xor_sync(0xffffffffu, maxsq, off));
        dmax = (maxsq > 0.f) ? sqrtf(maxsq) : 0.f;
    }

    // hot loop: per-lane sorted top-4 ascending by (f, j); f is sq (allValid)
    float f0 = FLT_MAX, f1 = FLT_MAX, f2 = FLT_MAX, f3 = FLT_MAX;
    int   j0 = JSENT,   j1 = JSENT,   j2 = JSENT,   j3 = JSENT;
    #pragma unroll 8
    for (int c = 0; c < 64; c++) {
        int j = c*32 + lane;
        float4 p = sX[j];
        float dx = p.x-qx, dy = p.y-qy, dz = p.z-qz;
        float sq = fmaf(dx,dx, fmaf(dy,dy, fmaf(dz,dz, 1e-6f)));
        float dv;
        if (allValid) dv = sq;                           // sqrt deferred
        else dv = (qvalid && (p.w > 0.5f)) ? sqrtf(sq) : dmax;
        if (dv < f3) {
            f3 = dv; j3 = j;
            if (f3 < f2) { float t=f2; f2=f3; f3=t; int u=j2; j2=j3; j3=u; }
            if (f2 < f1) { float t=f1; f1=f2; f2=t; int u=j1; j1=j2; j2=u; }
            if (f1 < f0) { float t=f0; f0=f1; f1=t; int u=j0; j0=j1; j1=u; }
        }
    }
    // convert survivors to sqrt domain and restore exact (f, j) order
    if (allValid) { f0 = sqrtf(f0); f1 = sqrtf(f1); f2 = sqrtf(f2); f3 = sqrtf(f3); }
    SWP(f0,j0,f1,j1); SWP(f2,j2,f3,j3); SWP(f0,j0,f2,j2); SWP(f1,j1,f3,j3); SWP(f1,j1,f2,j2);

    unsigned long long popped = 0ull;

    #pragma unroll 1
    for (int k = 0; k < KNB; k++) {
        unsigned kf = __float_as_uint(f0);              // nonneg -> monotone bits
        unsigned m  = __reduce_min_sync(0xffffffffu, kf);
        unsigned cand = (kf == m) ? (unsigned)j0 : 0xFFFFFFFFu;
        unsigned wj = __reduce_min_sync(0xffffffffu, cand);
        if (lane == 0) {
            g_E[q*KNB + k] = (int)wj;
            if (writeTail) tail[q*KNB + k] = (float)wj;
        }
        if ((wj & 31u) == (unsigned)lane) {             // owner pops its head
            popped |= 1ull << (wj >> 5);
            f0=f1; j0=j1; f1=f2; j1=j2; f2=f3; j2=j3; f3=FLT_MAX; j3=JSENT;
            if (f0 == FLT_MAX) {
                // refill (rare): rescan un-popped candidates
                for (int c = 0; c < 64; c++) {
                    if (popped & (1ull << c)) continue;
                    int j = c*32 + lane;
                    float4 p = sX[j];
                    float dx = p.x-qx, dy = p.y-qy, dz = p.z-qz;
                    float sq = fmaf(dx,dx, fmaf(dy,dy, fmaf(dz,dz, 1e-6f)));
                    float dv;
                    if (allValid) dv = sq;
                    else dv = (qvalid && (p.w > 0.5f)) ? sqrtf(sq) : dmax;
                    if (dv < f3) {
                        f3 = dv; j3 = j;
                        if (f3 < f2) { float t=f2; f2=f3; f3=t; int u=j2; j2=j3; j3=u; }
                        if (f2 < f1) { float t=f1; f1=f2; f2=t; int u=j1; j1=j2; j2=u; }
                        if (f1 < f0) { float t=f0; f0=f1; f1=t; int u=j0; j0=j1; j1=u; }
                    }
                }
                if (allValid) { f0=sqrtf(f0); f1=sqrtf(f1); f2=sqrtf(f2); f3=sqrtf(f3); }
                SWP(f0,j0,f1,j1); SWP(f2,j2,f3,j3); SWP(f0,j0,f2,j2);
                SWP(f1,j1,f3,j3); SWP(f1,j1,f2,j2);
            }
        }
    }
}

// ---------------------------------------------------------------------------
// GEMM: g_A = V @ W[:128] + bias ; g_Bm = V @ W[128:]
// ---------------------------------------------------------------------------
__global__ void gemm_kernel(const float* __restrict__ V,
                            const float* __restrict__ W,
                            const float* __restrict__ bias)
{
    __shared__ float sV[16][132];
    __shared__ float sW[16][64];

    int rb   = blockIdx.x * 128;
    int cb   = blockIdx.y;
    int half = (cb >= 7) ? 1 : 0;
    int o0   = (cb - half*7) * 64;
    int koff = half * 128;
    float* out = half ? g_Bm : g_A;

    int tid = threadIdx.x;
    int ty = tid >> 4;
    int tx = tid & 15;

    float acc[8][4];
    #pragma unroll
    for (int r = 0; r < 8; r++)
        #pragma unroll
        for (int c = 0; c < 4; c++) acc[r][c] = 0.f;

    for (int kt = 0; kt < IND; kt += 16) {
        {
            int rr = tid & 127;
            int v  = tid >> 7;
            const float* src = V + (size_t)(rb + rr)*IND + kt + v*8;
            float4 a  = *(const float4*)src;
            float4 b2 = *(const float4*)(src + 4);
            int kk = v * 8;
            sV[kk+0][rr]=a.x;  sV[kk+1][rr]=a.y;  sV[kk+2][rr]=a.z;  sV[kk+3][rr]=a.w;
            sV[kk+4][rr]=b2.x; sV[kk+5][rr]=b2.y; sV[kk+6][rr]=b2.z; sV[kk+7][rr]=b2.w;
        }
        {
            int kk = tid >> 4;
            int cc = (tid & 15) * 4;
            int o  = o0 + cc;
            const float* wrow = W + (size_t)(kt + kk + koff)*OUTD;
            float4 wv;
            if (o + 3 < OUTD) {
                wv = *(const float4*)(wrow + o);
            } else {
                wv.x = (o+0 < OUTD) ? wrow[o+0] : 0.f;
                wv.y = (o+1 < OUTD) ? wrow[o+1] : 0.f;
                wv.z = (o+2 < OUTD) ? wrow[o+2] : 0.f;
                wv.w = (o+3 < OUTD) ? wrow[o+3] : 0.f;
            }
            *(float4*)&sW[kk][cc] = wv;
        }
        __syncthreads();

        #pragma unroll
        for (int kk = 0; kk < 16; kk++) {
            float rv[8];
            *(float4*)&rv[0] = *(const float4*)&sV[kk][ty*8];
            *(float4*)&rv[4] = *(const float4*)&sV[kk][ty*8 + 4];
            float4 wv = *(const float4*)&sW[kk][tx*4];
            #pragma unroll
            for (int r = 0; r < 8; r++) {
                acc[r][0] += rv[r] * wv.x;
                acc[r][1] += rv[r] * wv.y;
                acc[r][2] += rv[r] * wv.z;
                acc[r][3] += rv[r] * wv.w;
            }
        }
        __syncthreads();
    }

    #pragma unroll
    for (int r = 0; r < 8; r++) {
        int row = rb + ty*8 + r;
        #pragma unroll
        for (int c = 0; c < 4; c++) {
            int o = o0 + tx*4 + c;
            if (o < OUTD) {
                float val = acc[r][c];
                if (!half) val += bias[o];
                out[(size_t)row*OUTD + o] = val;
            }
        }
    }
}

// ---------------------------------------------------------------------------
// Assembly: out[q,k,:] = A[row_i0,:] + Bm[row_jk,:]
// 2 queries per 512-thread block; fully unrolled 12-deep gather loop for MLP;
// __stcs streaming stores keep the 393MB output stream from evicting the
// L2-resident gather tables.
// ---------------------------------------------------------------------------
__global__ __launch_bounds__(512) void assemble_kernel(float* __restrict__ out)
{
    __shared__ float4 sA[2][100];
    __shared__ int    sI[2][KNB];

    int tid  = threadIdx.x;
    int half = tid >> 8;            // which query within block
    int t    = tid & 255;
    int q    = blockIdx.x * 2 + half;
    int b    = q >> 11;

    if (t < KNB) sI[half][t] = g_E[q*KNB + t];
    __syncthreads();
    int e0 = sI[half][0];
    if (t < 100)
        sA[half][t] = ((const float4*)g_A)[(size_t)((b << 11) + e0)*100 + t];
    __syncthreads();

    float4* out4 = (float4*)out + (size_t)q * (KNB*100);
    const float4* B4 = (const float4*)g_Bm;

    #pragma unroll
    for (int it = 0; it < 12; it++) {
        int id = t + it*256;
        if (id < KNB*100) {
            int k = id / 100;
            int c = id - k*100;
            int rj = (b << 11) + sI[half][k];
            float4 a  = sA[half][c];
            float4 bb = __ldg(&B4[(size_t)rj*100 + c]);
            float4 r;
            r.x = a.x + bb.x; r.y = a.y + bb.y;
            r.z = a.z + bb.z; r.w = a.w + bb.w;
            __stcs(&out4[id], r);
        }
    }
}

// ---------------------------------------------------------------------------
extern "C" void kernel_launch(void* const* d_in, const int* in_sizes, int n_in,
                              void* d_out, int out_size)
{
    const float* X    = (const float*)d_in[0];
    const float* mask = (const float*)d_in[1];
    const float* V    = (const float*)d_in[2];
    const float* W    = (const float*)d_in[3];
    const float* bias = (const float*)d_in[4];
    float* out = (float*)d_out;

    const long long HEV  = (long long)NROW * KNB * OUTD;  // 98,304,000
    const long long EIDX = (long long)NROW * KNB;         // 245,760
    int writeTail = ((long long)out_size >= HEV + EIDX) ? 1 : 0;
    float* tail = writeTail ? (out + HEV) : nullptr;

    // one-time side-stream setup (no device memory involved)
    static cudaStream_t s2 = nullptr;
    static cudaEvent_t eFork = nullptr, eJoin = nullptr;
    static int streamsOK = -1;
    if (streamsOK < 0) {
        streamsOK = 1;
        if (cudaStreamCreateWithFlags(&s2, cudaStreamNonBlocking) != cudaSuccess) streamsOK = 0;
        if (streamsOK && cudaEventCreateWithFlags(&eFork, cudaEventDisableTiming) != cudaSuccess) streamsOK = 0;
        if (streamsOK && cudaEventCreateWithFlags(&eJoin, cudaEventDisableTiming) != cudaSuccess) streamsOK = 0;
    }

    if (streamsOK) {
        // fork: gemm runs concurrently with knn
        cudaEventRecord(eFork, 0);
        cudaStreamWaitEvent(s2, eFork, 0);
        knn_kernel<<<NROW/16, 512>>>(X, mask, tail, writeTail);
        gemm_kernel<<<dim3(NROW/128, 14), 256, 0, s2>>>(V, W, bias);
        cudaEventRecord(eJoin, s2);
        cudaStreamWaitEvent(0, eJoin, 0);
        assemble_kernel<<<NROW/2, 512>>>(out);
    } else {
        knn_kernel<<<NROW/16, 512>>>(X, mask, tail, writeTail);
        gemm_kernel<<<dim3(NROW/128, 14), 256>>>(V, W, bias);
        assemble_kernel<<<NROW/2, 512>>>(out);
    }
}